// round 3
// baseline (speedup 1.0000x reference)
#include <cuda_runtime.h>
#include <math.h>

// Problem constants (fixed by the dataset)
#define NQTOT  7200      // B*N = 8*900
#define NPERB  900
#define CDIM   256
#define HEADS  8
#define NPTS   4
#define HD     32
#define BEV    200
#define HW     40000     // 200*200

#define BQ     32        // queries per block in kernel 1
#define K1BLOCKS (NQTOT / BQ)   // 225

// dynamic smem layout for kernel 1 (floats):
//  [0,     8224): qs   (32 rows x 257, padded)   -- reused after GEMM:
//        Px0 int[1024] @ +0
//        Py0 int[1024] @ +1024
//        Pfx f32[1024] @ +2048
//        Pfy f32[1024] @ +3072
//        Wt  f32[1024] @ +4096
//  [8224,  9760): Ws   (16 x 96)
//  [9760, 12832): S    (32 x 96)   offsets(64) | logits(32)
//  [12832,12896): refs (32 x 2)
#define SM_FLOATS 12896
#define SM_BYTES  (SM_FLOATS * 4)

__device__ float g_fused[(size_t)NQTOT * CDIM];

__global__ __launch_bounds__(256) void k1_offsets_sample(
    const float* __restrict__ query,
    const float* __restrict__ memory,
    const float* __restrict__ refpts,
    const float* __restrict__ w_off,
    const float* __restrict__ b_off,
    const float* __restrict__ w_wt,
    const float* __restrict__ b_wt)
{
    extern __shared__ float sm[];
    float* qs   = sm;
    float* Ws   = sm + 8224;
    float* S    = sm + 9760;
    float* refs = sm + 12832;

    const int t = threadIdx.x;
    const int qbase = blockIdx.x * BQ;

    // ---- load 32 query rows + reference points ----
    #pragma unroll
    for (int i = 0; i < 32; i++) {
        int idx = i * 256 + t;
        int r = idx >> 8, k = idx & 255;
        qs[r * 257 + k] = query[(size_t)(qbase + r) * CDIM + k];
    }
    if (t < 64) refs[t] = refpts[(size_t)qbase * 2 + t];

    // ---- GEMM: S[32,96] = q[32,256] @ [w_off | w_wt] ----
    const int rg = t >> 4;          // 0..15 -> rows 2*rg, 2*rg+1
    const int cg = t & 15;          // 0..15 -> cols cg*6 .. +5
    const int r0 = rg * 2, r1 = r0 + 1;
    const int c0 = cg * 6;

    float acc0[6] = {0,0,0,0,0,0};
    float acc1[6] = {0,0,0,0,0,0};

    for (int kt = 0; kt < 16; kt++) {
        __syncthreads();
        #pragma unroll
        for (int i = 0; i < 6; i++) {
            int idx = i * 256 + t;           // 0..1535
            int k = idx / 96, c = idx - k * 96;
            int kg = kt * 16 + k;
            Ws[idx] = (c < 64) ? w_off[kg * 64 + c] : w_wt[kg * 32 + (c - 64)];
        }
        __syncthreads();
        #pragma unroll
        for (int k = 0; k < 16; k++) {
            float q0 = qs[r0 * 257 + kt * 16 + k];
            float q1 = qs[r1 * 257 + kt * 16 + k];
            const float* wrow = &Ws[k * 96 + c0];
            #pragma unroll
            for (int j = 0; j < 6; j++) {
                float w = wrow[j];
                acc0[j] += q0 * w;
                acc1[j] += q1 * w;
            }
        }
    }

    // epilogue: bias + tanh*0.2 for offsets, bias for logits
    #pragma unroll
    for (int j = 0; j < 6; j++) {
        int c = c0 + j;
        float v0, v1;
        if (c < 64) {
            float b = b_off[c];
            v0 = tanhf(acc0[j] + b) * 0.2f;
            v1 = tanhf(acc1[j] + b) * 0.2f;
        } else {
            float b = b_wt[c - 64];
            v0 = acc0[j] + b;
            v1 = acc1[j] + b;
        }
        S[r0 * 96 + c] = v0;
        S[r1 * 96 + c] = v1;
    }
    __syncthreads();

    // ---- per-(query, head*P+p) sampling params (reuse qs region) ----
    int*   Px0 = (int*)sm;
    int*   Py0 = (int*)(sm + 1024);
    float* Pfx = sm + 2048;
    float* Pfy = sm + 3072;
    float* Wt  = sm + 4096;

    #pragma unroll
    for (int it = t; it < BQ * 32; it += 256) {
        int q = it >> 5, pr = it & 31;
        float offx = S[q * 96 + pr * 2 + 0];
        float offy = S[q * 96 + pr * 2 + 1];
        float x = (refs[q * 2 + 0] + offx) * (float)BEV - 0.5f;
        float y = (refs[q * 2 + 1] + offy) * (float)BEV - 0.5f;
        float x0f = floorf(x), y0f = floorf(y);
        Px0[it] = (int)x0f;
        Py0[it] = (int)y0f;
        Pfx[it] = x - x0f;
        Pfy[it] = y - y0f;
    }
    // softmax over P per (query, head): exactly 256 items
    {
        int q = t >> 3, h = t & 7;
        float l0 = S[q * 96 + 64 + h * 4 + 0];
        float l1 = S[q * 96 + 64 + h * 4 + 1];
        float l2 = S[q * 96 + 64 + h * 4 + 2];
        float l3 = S[q * 96 + 64 + h * 4 + 3];
        float m = fmaxf(fmaxf(l0, l1), fmaxf(l2, l3));
        float e0 = __expf(l0 - m), e1 = __expf(l1 - m);
        float e2 = __expf(l2 - m), e3 = __expf(l3 - m);
        float inv = 1.0f / (e0 + e1 + e2 + e3);
        Wt[q * 32 + h * 4 + 0] = e0 * inv;
        Wt[q * 32 + h * 4 + 1] = e1 * inv;
        Wt[q * 32 + h * 4 + 2] = e2 * inv;
        Wt[q * 32 + h * 4 + 3] = e3 * inv;
    }
    __syncthreads();

    // ---- bilinear sampling + weighted sum over P ----
    const int head = t >> 5;        // channel = head*32 + (t&31) = t
    for (int q = 0; q < BQ; q++) {
        int g = qbase + q;
        const float* memb = memory + (size_t)(g / NPERB) * HW * CDIM;
        float acc = 0.0f;
        #pragma unroll
        for (int p = 0; p < NPTS; p++) {
            int idx = q * 32 + head * 4 + p;
            int x0 = Px0[idx], y0 = Py0[idx];
            float fx = Pfx[idx], fy = Pfy[idx];
            float wt = Wt[idx];
            bool xv0 = (unsigned)x0 < (unsigned)BEV;
            bool xv1 = (unsigned)(x0 + 1) < (unsigned)BEV;
            bool yv0 = (unsigned)y0 < (unsigned)BEV;
            bool yv1 = (unsigned)(y0 + 1) < (unsigned)BEV;
            const float* rowp = memb + ((long)y0 * BEV + x0) * CDIM + t;
            float v00 = 0.f, v01 = 0.f, v10 = 0.f, v11 = 0.f;
            if (yv0 && xv0) v00 = __ldg(rowp);
            if (yv0 && xv1) v01 = __ldg(rowp + CDIM);
            if (yv1 && xv0) v10 = __ldg(rowp + BEV * CDIM);
            if (yv1 && xv1) v11 = __ldg(rowp + BEV * CDIM + CDIM);
            float gx1 = 1.0f - fx, gy1 = 1.0f - fy;
            acc += wt * (gx1 * gy1 * v00 + fx * gy1 * v01 +
                         gx1 * fy  * v10 + fx * fy  * v11);
        }
        g_fused[(size_t)g * CDIM + t] = acc;
    }
}

// out[7200,256] = g_fused[7200,256] @ w_out[256,256] + b_out
__global__ __launch_bounds__(256) void k2_outproj(
    const float* __restrict__ w_out,
    const float* __restrict__ b_out,
    float* __restrict__ out)
{
    __shared__ float As[64][17];
    __shared__ float Bs[16][64];

    const int t  = threadIdx.x;
    const int tx = t & 15, ty = t >> 4;
    const int bm = blockIdx.y, bn = blockIdx.x;

    const int arow = t >> 2;          // 0..63
    const int ak   = (t & 3) * 4;     // 0,4,8,12
    const int brow = t >> 4;          // 0..15
    const int bcol = (t & 15) * 4;    // 0..60

    float acc[4][4] = {};

    for (int kt = 0; kt < 16; kt++) {
        int m = bm * 64 + arow;
        float4 av = make_float4(0.f, 0.f, 0.f, 0.f);
        if (m < NQTOT)
            av = *(const float4*)&g_fused[(size_t)m * CDIM + kt * 16 + ak];
        As[arow][ak + 0] = av.x;
        As[arow][ak + 1] = av.y;
        As[arow][ak + 2] = av.z;
        As[arow][ak + 3] = av.w;

        float4 bv = *(const float4*)&w_out[(size_t)(kt * 16 + brow) * CDIM + bn * 64 + bcol];
        *(float4*)&Bs[brow][bcol] = bv;

        __syncthreads();
        #pragma unroll
        for (int k = 0; k < 16; k++) {
            float4 b4 = *(float4*)&Bs[k][tx * 4];
            float bb[4] = {b4.x, b4.y, b4.z, b4.w};
            #pragma unroll
            for (int i = 0; i < 4; i++) {
                float a = As[ty * 4 + i][k];
                #pragma unroll
                for (int j = 0; j < 4; j++) acc[i][j] += a * bb[j];
            }
        }
        __syncthreads();
    }

    #pragma unroll
    for (int i = 0; i < 4; i++) {
        int m = bm * 64 + ty * 4 + i;
        if (m < NQTOT) {
            #pragma unroll
            for (int j = 0; j < 4; j++) {
                int n = bn * 64 + tx * 4 + j;
                out[(size_t)m * CDIM + n] = acc[i][j] + b_out[n];
            }
        }
    }
}

extern "C" void kernel_launch(void* const* d_in, const int* in_sizes, int n_in,
                              void* d_out, int out_size)
{
    const float* query  = (const float*)d_in[0];
    const float* memory = (const float*)d_in[1];
    const float* refpts = (const float*)d_in[2];
    const float* w_off  = (const float*)d_in[3];
    const float* b_off  = (const float*)d_in[4];
    const float* w_wt   = (const float*)d_in[5];
    const float* b_wt   = (const float*)d_in[6];
    const float* w_out  = (const float*)d_in[7];
    const float* b_out  = (const float*)d_in[8];
    float* out = (float*)d_out;

    cudaFuncSetAttribute(k1_offsets_sample,
                         cudaFuncAttributeMaxDynamicSharedMemorySize, SM_BYTES);

    k1_offsets_sample<<<K1BLOCKS, 256, SM_BYTES>>>(
        query, memory, refpts, w_off, b_off, w_wt, b_wt);

    dim3 g2(CDIM / 64, (NQTOT + 63) / 64);   // (4, 113)
    k2_outproj<<<g2, 256>>>(w_out, b_out, out);
}

// round 7
// speedup vs baseline: 1.0449x; 1.0449x over previous
#include <cuda_runtime.h>
#include <math.h>

// Problem constants (fixed by the dataset)
#define NQTOT  7200      // B*N = 8*900
#define NPERB  900
#define CDIM   256
#define HEADS  8
#define NPTS   4
#define BEV    200
#define HW     40000     // 200*200

#define BQ     32        // queries per block in kernel 1
#define K1BLOCKS (NQTOT / BQ)   // 225

// dynamic smem layout for kernel 1 (floats):
//  [0,     8224): qs (32 x 257) during GEMM; reused after as:
//        Idx int4[1024]   @ +0     (4096 floats)
//        Wc  float4[1024] @ +4096  (4096 floats)
//  [8224,  9760): Ws   (16 x 96)
//  [9760, 12832): S    (32 x 96)   offsets(64) | logits->probs(32)
//  [12832,12896): refs (32 x 2)
#define SM_FLOATS 12896
#define SM_BYTES  (SM_FLOATS * 4)

__device__ float g_fused[(size_t)NQTOT * CDIM];

__global__ __launch_bounds__(256) void k1_offsets_sample(
    const float* __restrict__ query,
    const float* __restrict__ memory,
    const float* __restrict__ refpts,
    const float* __restrict__ w_off,
    const float* __restrict__ b_off,
    const float* __restrict__ w_wt,
    const float* __restrict__ b_wt)
{
    extern __shared__ float sm[];
    float* qs   = sm;
    float* Ws   = sm + 8224;
    float* S    = sm + 9760;
    float* refs = sm + 12832;

    const int t = threadIdx.x;
    const int qbase = blockIdx.x * BQ;

    // ---- load 32 query rows + reference points ----
    #pragma unroll
    for (int i = 0; i < 32; i++) {
        int idx = i * 256 + t;
        int r = idx >> 8, k = idx & 255;
        qs[r * 257 + k] = query[(size_t)(qbase + r) * CDIM + k];
    }
    if (t < 64) refs[t] = refpts[(size_t)qbase * 2 + t];

    // ---- GEMM: S[32,96] = q[32,256] @ [w_off | w_wt] ----
    const int rg = t >> 4;          // 0..15 -> rows 2*rg, 2*rg+1
    const int cg = t & 15;          // 0..15 -> cols cg*6 .. +5
    const int r0 = rg * 2, r1 = r0 + 1;
    const int c0 = cg * 6;

    float acc0[6] = {0,0,0,0,0,0};
    float acc1[6] = {0,0,0,0,0,0};

    for (int kt = 0; kt < 16; kt++) {
        __syncthreads();
        #pragma unroll
        for (int i = 0; i < 6; i++) {
            int idx = i * 256 + t;           // 0..1535
            int k = idx / 96, c = idx - k * 96;
            int kg = kt * 16 + k;
            Ws[idx] = (c < 64) ? w_off[kg * 64 + c] : w_wt[kg * 32 + (c - 64)];
        }
        __syncthreads();
        #pragma unroll
        for (int k = 0; k < 16; k++) {
            float q0 = qs[r0 * 257 + kt * 16 + k];
            float q1 = qs[r1 * 257 + kt * 16 + k];
            const float* wrow = &Ws[k * 96 + c0];
            #pragma unroll
            for (int j = 0; j < 6; j++) {
                float w = wrow[j];
                acc0[j] += q0 * w;
                acc1[j] += q1 * w;
            }
        }
    }

    // epilogue: bias + tanh*0.2 for offsets, bias for logits
    #pragma unroll
    for (int j = 0; j < 6; j++) {
        int c = c0 + j;
        float v0, v1;
        if (c < 64) {
            float b = b_off[c];
            v0 = tanhf(acc0[j] + b) * 0.2f;
            v1 = tanhf(acc1[j] + b) * 0.2f;
        } else {
            float b = b_wt[c - 64];
            v0 = acc0[j] + b;
            v1 = acc1[j] + b;
        }
        S[r0 * 96 + c] = v0;
        S[r1 * 96 + c] = v1;
    }
    __syncthreads();

    // ---- softmax over P per (query, head), in place in S ----
    {
        int q = t >> 3, h = t & 7;
        float* lp = &S[q * 96 + 64 + h * 4];
        float l0 = lp[0], l1 = lp[1], l2 = lp[2], l3 = lp[3];
        float m = fmaxf(fmaxf(l0, l1), fmaxf(l2, l3));
        float e0 = __expf(l0 - m), e1 = __expf(l1 - m);
        float e2 = __expf(l2 - m), e3 = __expf(l3 - m);
        float inv = 1.0f / (e0 + e1 + e2 + e3);
        lp[0] = e0 * inv; lp[1] = e1 * inv;
        lp[2] = e2 * inv; lp[3] = e3 * inv;
    }
    __syncthreads();

    // ---- precompute per-(q, head, p): 4 clamped prescaled offsets + 4 fused weights ----
    int4*   Idx = (int4*)sm;
    float4* Wc  = (float4*)(sm + 4096);

    #pragma unroll
    for (int it = t; it < BQ * 32; it += 256) {
        int q = it >> 5, pr = it & 31;           // pr = head*4 + p
        float offx = S[q * 96 + pr * 2 + 0];
        float offy = S[q * 96 + pr * 2 + 1];
        float wt   = S[q * 96 + 64 + pr];
        float x = (refs[q * 2 + 0] + offx) * (float)BEV - 0.5f;
        float y = (refs[q * 2 + 1] + offy) * (float)BEV - 0.5f;
        float x0f = floorf(x), y0f = floorf(y);
        int x0 = (int)x0f, y0 = (int)y0f;
        float fx = x - x0f, fy = y - y0f;

        float xv0 = ((unsigned)x0       < (unsigned)BEV) ? 1.f : 0.f;
        float xv1 = ((unsigned)(x0 + 1) < (unsigned)BEV) ? 1.f : 0.f;
        float yv0 = ((unsigned)y0       < (unsigned)BEV) ? 1.f : 0.f;
        float yv1 = ((unsigned)(y0 + 1) < (unsigned)BEV) ? 1.f : 0.f;

        int xc0 = min(max(x0, 0),     BEV - 1);
        int xc1 = min(max(x0 + 1, 0), BEV - 1);
        int yc0 = min(max(y0, 0),     BEV - 1);
        int yc1 = min(max(y0 + 1, 0), BEV - 1);

        int4 id;
        id.x = (yc0 * BEV + xc0) * CDIM;
        id.y = (yc0 * BEV + xc1) * CDIM;
        id.z = (yc1 * BEV + xc0) * CDIM;
        id.w = (yc1 * BEV + xc1) * CDIM;

        float gx1 = 1.0f - fx, gy1 = 1.0f - fy;
        float4 w;
        w.x = wt * gx1 * gy1 * (xv0 * yv0);
        w.y = wt * fx  * gy1 * (xv1 * yv0);
        w.z = wt * gx1 * fy  * (xv0 * yv1);
        w.w = wt * fx  * fy  * (xv1 * yv1);

        Idx[it] = id;
        Wc[it]  = w;
    }
    __syncthreads();

    // ---- bilinear sampling + weighted sum over P ----
    // NOTE: batch index MUST be computed per query — NPERB (900) is not a
    // multiple of BQ (32), so a block can straddle a batch boundary.
    const int head = t >> 5;        // channel = t (head*32 + lane)
    #pragma unroll 2
    for (int q = 0; q < BQ; q++) {
        int g = qbase + q;
        const float* memb = memory + (size_t)(g / NPERB) * HW * CDIM + t;
        float acc = 0.0f;
        #pragma unroll
        for (int p = 0; p < NPTS; p++) {
            int ii = q * 32 + head * 4 + p;
            int4   id = Idx[ii];
            float4 w  = Wc[ii];
            float v00 = __ldg(memb + id.x);
            float v01 = __ldg(memb + id.y);
            float v10 = __ldg(memb + id.z);
            float v11 = __ldg(memb + id.w);
            acc += w.x * v00 + w.y * v01 + w.z * v10 + w.w * v11;
        }
        g_fused[(size_t)g * CDIM + t] = acc;
    }
}

// out[7200,256] = g_fused[7200,256] @ w_out[256,256] + b_out
__global__ __launch_bounds__(256) void k2_outproj(
    const float* __restrict__ w_out,
    const float* __restrict__ b_out,
    float* __restrict__ out)
{
    __shared__ float As[16][68];   // k-major, padded (272B rows: float4-aligned, banks spread)
    __shared__ float Bs[16][64];

    const int t  = threadIdx.x;
    const int tx = t & 15, ty = t >> 4;
    const int bm = blockIdx.y, bn = blockIdx.x;

    const int arow = t >> 2;          // 0..63  (m within tile)
    const int ak   = (t & 3) * 4;     // 0,4,8,12 (k base)
    const int brow = t >> 4;          // 0..15
    const int bcol = (t & 15) * 4;    // 0..60

    float acc[4][4] = {};

    for (int kt = 0; kt < 16; kt++) {
        int m = bm * 64 + arow;
        float4 av = make_float4(0.f, 0.f, 0.f, 0.f);
        if (m < NQTOT)
            av = *(const float4*)&g_fused[(size_t)m * CDIM + kt * 16 + ak];
        // transpose into k-major As[k][m]
        As[ak + 0][arow] = av.x;
        As[ak + 1][arow] = av.y;
        As[ak + 2][arow] = av.z;
        As[ak + 3][arow] = av.w;

        float4 bv = *(const float4*)&w_out[(size_t)(kt * 16 + brow) * CDIM + bn * 64 + bcol];
        *(float4*)&Bs[brow][bcol] = bv;

        __syncthreads();
        #pragma unroll
        for (int k = 0; k < 16; k++) {
            float4 a4 = *(const float4*)&As[k][ty * 4];
            float4 b4 = *(const float4*)&Bs[k][tx * 4];
            float aa[4] = {a4.x, a4.y, a4.z, a4.w};
            float bb[4] = {b4.x, b4.y, b4.z, b4.w};
            #pragma unroll
            for (int i = 0; i < 4; i++)
                #pragma unroll
                for (int j = 0; j < 4; j++)
                    acc[i][j] += aa[i] * bb[j];
        }
        __syncthreads();
    }

    #pragma unroll
    for (int i = 0; i < 4; i++) {
        int m = bm * 64 + ty * 4 + i;
        if (m < NQTOT) {
            #pragma unroll
            for (int j = 0; j < 4; j++) {
                int n = bn * 64 + tx * 4 + j;
                out[(size_t)m * CDIM + n] = acc[i][j] + b_out[n];
            }
        }
    }
}

extern "C" void kernel_launch(void* const* d_in, const int* in_sizes, int n_in,
                              void* d_out, int out_size)
{
    const float* query  = (const float*)d_in[0];
    const float* memory = (const float*)d_in[1];
    const float* refpts = (const float*)d_in[2];
    const float* w_off  = (const float*)d_in[3];
    const float* b_off  = (const float*)d_in[4];
    const float* w_wt   = (const float*)d_in[5];
    const float* b_wt   = (const float*)d_in[6];
    const float* w_out  = (const float*)d_in[7];
    const float* b_out  = (const float*)d_in[8];
    float* out = (float*)d_out;

    cudaFuncSetAttribute(k1_offsets_sample,
                         cudaFuncAttributeMaxDynamicSharedMemorySize, SM_BYTES);

    k1_offsets_sample<<<K1BLOCKS, 256, SM_BYTES>>>(
        query, memory, refpts, w_off, b_off, w_wt, b_wt);

    dim3 g2(CDIM / 64, (NQTOT + 63) / 64);   // (4, 113)
    k2_outproj<<<g2, 256>>>(w_out, b_out, out);
}